// round 5
// baseline (speedup 1.0000x reference)
#include <cuda_runtime.h>

typedef unsigned long long ull;

#define BATCH 4096

// ---------------- device scratch (no allocations allowed) ----------------
__device__ float g_h  [BATCH * 512];
__device__ float g_qx [BATCH * 512];
__device__ float g_qW2[512 * 512];
__device__ float g_h2 [BATCH * 512];
__device__ float g_qx2[BATCH * 512];
__device__ double g_bnsum[512];
__device__ double g_bnsq [512];
__device__ double g_dsum[3];   // [0]=fq21 sum, [1]=wq sum, [2]=fq22 sum

// ---------------- packed f32x2 helpers (Blackwell FFMA2) ----------------
__device__ __forceinline__ ull pack2(float x, float y) {
    ull r;
    unsigned xu = __float_as_uint(x), yu = __float_as_uint(y);
    asm("mov.b64 %0, {%1, %2};" : "=l"(r) : "r"(xu), "r"(yu));
    return r;
}
__device__ __forceinline__ float2 unpack2(ull v) {
    unsigned lo, hi;
    asm("mov.b64 {%0, %1}, %2;" : "=r"(lo), "=r"(hi) : "l"(v));
    float2 f; f.x = __uint_as_float(lo); f.y = __uint_as_float(hi);
    return f;
}
__device__ __forceinline__ ull ffma2(ull a, ull b, ull c) {
    ull d;
    asm("fma.rn.f32x2 %0, %1, %2, %3;" : "=l"(d) : "l"(a), "l"(b), "l"(c));
    return d;
}

// ---------------- block reduce -> atomic double ----------------
__device__ __forceinline__ void block_sum_to(double* target, float v) {
    __shared__ float red[8];
    const int tid = threadIdx.x;
    #pragma unroll
    for (int o = 16; o; o >>= 1) v += __shfl_xor_sync(0xffffffffu, v, o);
    if ((tid & 31) == 0) red[tid >> 5] = v;
    __syncthreads();
    if (tid == 0) {
        float s = 0.f;
        #pragma unroll
        for (int w = 0; w < 8; w++) s += red[w];
        atomicAdd(target, (double)s);
    }
}

// ---------------- GEMM: C[m,n] = relu( sum_k f(A[m,k]) * W[n,k] ) ----------------
// BM=128, BN=64, BK=16, 256 threads, per-thread 4m x 8n with FFMA2 over n-pairs.
// AFFINE: A transformed as A*scale[k]+shift[k], scale/shift derived from g_bnsum/g_bnsq.
template<int KDIM, bool AFFINE>
__global__ __launch_bounds__(256, 3)
void gemm_kernel(const float* __restrict__ Aext, const float* __restrict__ Wext,
                 const float* __restrict__ gamma, const float* __restrict__ beta)
{
    const float* __restrict__ A = AFFINE ? (const float*)g_qx  : Aext;
    const float* __restrict__ W = AFFINE ? (const float*)g_qW2 : Wext;
    float*       __restrict__ C = AFFINE ? (float*)g_h2 : (float*)g_h;

    __shared__ __align__(16) float As[16][132];
    __shared__ __align__(16) float Bs[16][68];
    __shared__ __align__(16) float sScale[512];
    __shared__ __align__(16) float sShift[512];

    const int tid = threadIdx.x;
    const int tx  = tid & 7;    // n group (8 cols)
    const int ty  = tid >> 3;   // m group (4 rows)
    const int m0  = blockIdx.y * 128;
    const int n0  = blockIdx.x * 64;

    if (AFFINE) {
        for (int c = tid; c < 512; c += 256) {
            float S  = (float)g_bnsum[c];
            float S2 = (float)g_bnsq[c];
            float mu  = S * (1.f / BATCH);
            float var = fmaf(-mu, mu, S2 * (1.f / BATCH));
            float sc  = gamma[c] * rsqrtf(var + 1e-5f);
            sScale[c] = sc;
            sShift[c] = fmaf(-mu, sc, beta[c]);
        }
        __syncthreads();
    } else {
        // first kernel in the graph: zero all accumulators
        if (blockIdx.x == 0 && blockIdx.y == 0) {
            for (int i = tid; i < 512; i += 256) { g_bnsum[i] = 0.0; g_bnsq[i] = 0.0; }
            if (tid < 3) g_dsum[tid] = 0.0;
        }
    }

    ull acc[4][4];
    #pragma unroll
    for (int m = 0; m < 4; m++)
        #pragma unroll
        for (int p = 0; p < 4; p++) acc[m][p] = 0ull;

    for (int kt = 0; kt < KDIM; kt += 16) {
        // A tile (128 rows x 16 k): 512 float4 / 256 threads
        #pragma unroll
        for (int l = 0; l < 2; l++) {
            int i = tid + l * 256;
            int row = i >> 2, kq = i & 3;
            float4 av = *(const float4*)(A + (size_t)(m0 + row) * KDIM + kt + kq * 4);
            if (AFFINE) {
                float4 sc = *(const float4*)&sScale[kt + kq * 4];
                float4 sh = *(const float4*)&sShift[kt + kq * 4];
                av.x = fmaf(av.x, sc.x, sh.x);
                av.y = fmaf(av.y, sc.y, sh.y);
                av.z = fmaf(av.z, sc.z, sh.z);
                av.w = fmaf(av.w, sc.w, sh.w);
            }
            As[kq * 4 + 0][row] = av.x;
            As[kq * 4 + 1][row] = av.y;
            As[kq * 4 + 2][row] = av.z;
            As[kq * 4 + 3][row] = av.w;
        }
        // B tile (64 rows x 16 k): 256 float4 / 256 threads
        {
            int row = tid >> 2, kq = tid & 3;
            float4 bv = *(const float4*)(W + (size_t)(n0 + row) * KDIM + kt + kq * 4);
            Bs[kq * 4 + 0][row] = bv.x;
            Bs[kq * 4 + 1][row] = bv.y;
            Bs[kq * 4 + 2][row] = bv.z;
            Bs[kq * 4 + 3][row] = bv.w;
        }
        __syncthreads();

        #pragma unroll
        for (int k = 0; k < 16; k++) {
            const float4 av = *(const float4*)&As[k][ty * 4];
            ull a0 = pack2(av.x, av.x);
            ull a1 = pack2(av.y, av.y);
            ull a2 = pack2(av.z, av.z);
            ull a3 = pack2(av.w, av.w);
            ull b0 = *(const ull*)&Bs[k][tx * 8];
            ull b1 = *(const ull*)&Bs[k][tx * 8 + 2];
            ull b2 = *(const ull*)&Bs[k][tx * 8 + 4];
            ull b3 = *(const ull*)&Bs[k][tx * 8 + 6];
            acc[0][0] = ffma2(b0, a0, acc[0][0]);
            acc[0][1] = ffma2(b1, a0, acc[0][1]);
            acc[0][2] = ffma2(b2, a0, acc[0][2]);
            acc[0][3] = ffma2(b3, a0, acc[0][3]);
            acc[1][0] = ffma2(b0, a1, acc[1][0]);
            acc[1][1] = ffma2(b1, a1, acc[1][1]);
            acc[1][2] = ffma2(b2, a1, acc[1][2]);
            acc[1][3] = ffma2(b3, a1, acc[1][3]);
            acc[2][0] = ffma2(b0, a2, acc[2][0]);
            acc[2][1] = ffma2(b1, a2, acc[2][1]);
            acc[2][2] = ffma2(b2, a2, acc[2][2]);
            acc[2][3] = ffma2(b3, a2, acc[2][3]);
            acc[3][0] = ffma2(b0, a3, acc[3][0]);
            acc[3][1] = ffma2(b1, a3, acc[3][1]);
            acc[3][2] = ffma2(b2, a3, acc[3][2]);
            acc[3][3] = ffma2(b3, a3, acc[3][3]);
        }
        __syncthreads();
    }

    // epilogue: relu + store
    #pragma unroll
    for (int m = 0; m < 4; m++) {
        const int row = m0 + ty * 4 + m;
        float2 f0 = unpack2(acc[m][0]);
        float2 f1 = unpack2(acc[m][1]);
        float2 f2 = unpack2(acc[m][2]);
        float2 f3 = unpack2(acc[m][3]);
        float4 o0 = make_float4(fmaxf(f0.x, 0.f), fmaxf(f0.y, 0.f),
                                fmaxf(f1.x, 0.f), fmaxf(f1.y, 0.f));
        float4 o1 = make_float4(fmaxf(f2.x, 0.f), fmaxf(f2.y, 0.f),
                                fmaxf(f3.x, 0.f), fmaxf(f3.y, 0.f));
        *(float4*)(C + (size_t)row * 512 + n0 + tx * 8)     = o0;
        *(float4*)(C + (size_t)row * 512 + n0 + tx * 8 + 4) = o1;
    }
}

// ---------------- fq21: dim-8 VQ of h (strided groups) + fused BN stats ----------------
// vector (b,c): v_j = h[b, j*64+c].  4 vectors/thread, 4-code groups, group-min + index recovery.
__global__ __launch_bounds__(256, 2)
void fq21_kernel(const float* __restrict__ E)   // E: [8,512]
{
    __shared__ __align__(16) float sE[8][512];
    __shared__ __align__(16) float sC2[512];
    __shared__ float sBS[4][512];   // per-quadrant column sums
    __shared__ float sBQ[4][512];   // per-quadrant column sq-sums
    const int tid = threadIdx.x;
    for (int i = tid; i < 8 * 512; i += 256) ((float*)sE)[i] = E[i];
    __syncthreads();
    for (int e = tid; e < 512; e += 256) {
        float s = 0.f;
        #pragma unroll
        for (int j = 0; j < 8; j++) s = fmaf(sE[j][e], sE[j][e], s);
        sC2[e] = s;
    }
    __syncthreads();

    const int base = blockIdx.x * 1024 + tid;
    ull vr[4][8];
    #pragma unroll
    for (int s = 0; s < 4; s++) {
        const int vid = base + s * 256;
        const int b = vid >> 6, c = vid & 63;
        #pragma unroll
        for (int j = 0; j < 8; j++) {
            float v = g_h[(size_t)b * 512 + j * 64 + c];
            vr[s][j] = pack2(v, v);
        }
    }

    float bestd[4] = {1e30f, 1e30f, 1e30f, 1e30f};
    int   bg[4]    = {0, 0, 0, 0};
    const ull M2 = pack2(-2.f, -2.f);

    #pragma unroll 2
    for (int u = 0; u < 128; u++) {
        const ull c2A = *(const ull*)&sC2[4 * u];
        const ull c2B = *(const ull*)&sC2[4 * u + 2];
        ull a[4], b2[4];
        {
            const ull eA = *(const ull*)&sE[0][4 * u];
            const ull eB = *(const ull*)&sE[0][4 * u + 2];
            #pragma unroll
            for (int s = 0; s < 4; s++) {
                a [s] = ffma2(vr[s][0], eA, 0ull);
                b2[s] = ffma2(vr[s][0], eB, 0ull);
            }
        }
        #pragma unroll
        for (int j = 1; j < 8; j++) {
            const ull eA = *(const ull*)&sE[j][4 * u];
            const ull eB = *(const ull*)&sE[j][4 * u + 2];
            #pragma unroll
            for (int s = 0; s < 4; s++) {
                a [s] = ffma2(vr[s][j], eA, a [s]);
                b2[s] = ffma2(vr[s][j], eB, b2[s]);
            }
        }
        #pragma unroll
        for (int s = 0; s < 4; s++) {
            float2 fa = unpack2(ffma2(M2, a [s], c2A));
            float2 fb = unpack2(ffma2(M2, b2[s], c2B));
            float m = fminf(fminf(fa.x, fa.y), fminf(fb.x, fb.y));
            if (m < bestd[s]) { bestd[s] = m; bg[s] = u; }
        }
    }

    // index recovery + straight-through write + BN private accumulation
    float priv_s[8], priv_q[8];
    #pragma unroll
    for (int j = 0; j < 8; j++) { priv_s[j] = 0.f; priv_q[j] = 0.f; }
    float lsum = 0.f;
    #pragma unroll
    for (int s = 0; s < 4; s++) {
        const int u = bg[s];
        ull a = 0ull, b2 = 0ull;
        #pragma unroll
        for (int j = 0; j < 8; j++) {
            a  = ffma2(vr[s][j], *(const ull*)&sE[j][4 * u],     a);
            b2 = ffma2(vr[s][j], *(const ull*)&sE[j][4 * u + 2], b2);
        }
        float2 fa = unpack2(ffma2(M2, a,  *(const ull*)&sC2[4 * u]));
        float2 fb = unpack2(ffma2(M2, b2, *(const ull*)&sC2[4 * u + 2]));
        int e = 4 * u;
        if      (fa.x == bestd[s]) e += 0;
        else if (fa.y == bestd[s]) e += 1;
        else if (fb.x == bestd[s]) e += 2;
        else                       e += 3;

        const int vid = base + s * 256;
        const int b = vid >> 6, c = vid & 63;
        #pragma unroll
        for (int j = 0; j < 8; j++) {
            float v  = unpack2(vr[s][j]).x;
            float dq = sE[j][e] - v;
            lsum = fmaf(dq, dq, lsum);
            float qst = v + dq;                      // straight-through value (matches ref fp order)
            g_qx[(size_t)b * 512 + j * 64 + c] = qst;
            priv_s[j] += qst;
            priv_q[j]  = fmaf(qst, qst, priv_q[j]);
        }
    }

    // BN slab reduce: column = j*64 + (tid&63); quadrant q = tid>>6
    {
        const int q = tid >> 6, c = tid & 63;
        #pragma unroll
        for (int j = 0; j < 8; j++) {
            sBS[q][j * 64 + c] = priv_s[j];
            sBQ[q][j * 64 + c] = priv_q[j];
        }
    }
    __syncthreads();
    for (int cell = tid; cell < 512; cell += 256) {
        float s  = sBS[0][cell] + sBS[1][cell] + sBS[2][cell] + sBS[3][cell];
        float s2 = sBQ[0][cell] + sBQ[1][cell] + sBQ[2][cell] + sBQ[3][cell];
        atomicAdd(&g_bnsum[cell], (double)s);
        atomicAdd(&g_bnsq [cell], (double)s2);
    }
    block_sum_to(&g_dsum[0], lsum);
}

// ---------------- weight VQ of W2 (dim-16 groups), 4 threads per vector ----------------
// vector (g,c): v_k = W2[g*2+(k&1), c*8+(k>>1)], codebook embed_q2 [16,512].
__global__ __launch_bounds__(256)
void wq_kernel(const float* __restrict__ W2, const float* __restrict__ E)
{
    __shared__ __align__(16) float sE[16][512];
    __shared__ __align__(16) float sC2[512];
    const int tid = threadIdx.x;
    for (int i = tid; i < 16 * 512; i += 256) ((float*)sE)[i] = E[i];
    __syncthreads();
    for (int e = tid; e < 512; e += 256) {
        float s = 0.f;
        #pragma unroll
        for (int k = 0; k < 16; k++) s = fmaf(sE[k][e], sE[k][e], s);
        sC2[e] = s;
    }
    __syncthreads();

    const int vec   = blockIdx.x * 64 + (tid >> 2);   // 0..16383
    const int slice = tid & 3;
    const int g = vec >> 6, c = vec & 63;

    ull vr[16];
    #pragma unroll
    for (int k = 0; k < 16; k++) {
        float v = W2[(size_t)(g * 2 + (k & 1)) * 512 + c * 8 + (k >> 1)];
        vr[k] = pack2(v, v);
    }

    float bestd = 1e30f; int bg = slice;
    const ull M2 = pack2(-2.f, -2.f);
    // interleaved code groups: u = 4*uu + slice (bank-conflict-free across the 4 lanes)
    #pragma unroll 2
    for (int uu = 0; uu < 32; uu++) {
        const int u = 4 * uu + slice;
        ull a = 0ull, b2 = 0ull;
        #pragma unroll
        for (int k = 0; k < 16; k++) {
            a  = ffma2(vr[k], *(const ull*)&sE[k][4 * u],     a);
            b2 = ffma2(vr[k], *(const ull*)&sE[k][4 * u + 2], b2);
        }
        float2 fa = unpack2(ffma2(M2, a,  *(const ull*)&sC2[4 * u]));
        float2 fb = unpack2(ffma2(M2, b2, *(const ull*)&sC2[4 * u + 2]));
        float m = fminf(fminf(fa.x, fa.y), fminf(fb.x, fb.y));
        if (m < bestd) { bestd = m; bg = u; }
    }
    // per-slice index recovery
    int idx;
    {
        ull a = 0ull, b2 = 0ull;
        #pragma unroll
        for (int k = 0; k < 16; k++) {
            a  = ffma2(vr[k], *(const ull*)&sE[k][4 * bg],     a);
            b2 = ffma2(vr[k], *(const ull*)&sE[k][4 * bg + 2], b2);
        }
        float2 fa = unpack2(ffma2(M2, a,  *(const ull*)&sC2[4 * bg]));
        float2 fb = unpack2(ffma2(M2, b2, *(const ull*)&sC2[4 * bg + 2]));
        idx = 4 * bg;
        if      (fa.x == bestd) idx += 0;
        else if (fa.y == bestd) idx += 1;
        else if (fb.x == bestd) idx += 2;
        else                    idx += 3;
    }
    // combine across the 4 slice-lanes (lower distance, then lower index)
    #pragma unroll
    for (int off = 1; off < 4; off <<= 1) {
        float od = __shfl_xor_sync(0xffffffffu, bestd, off);
        int   oi = __shfl_xor_sync(0xffffffffu, idx,   off);
        if (od < bestd || (od == bestd && oi < idx)) { bestd = od; idx = oi; }
    }
    // each slice writes 4 dims
    #pragma unroll
    for (int kk = 0; kk < 4; kk++) {
        int k = slice * 4 + kk;
        float v  = unpack2(vr[k]).x;
        float dq = sE[k][idx] - v;
        g_qW2[(size_t)(g * 2 + (k & 1)) * 512 + c * 8 + (k >> 1)] = v + dq;
    }
    float lsum = 0.f;
    if (slice == 0) {
        #pragma unroll
        for (int k = 0; k < 16; k++) {
            float v  = unpack2(vr[k]).x;
            float dq = sE[k][idx] - v;
            lsum = fmaf(dq, dq, lsum);
        }
    }
    block_sum_to(&g_dsum[1], lsum);
}

// ---------------- fq22: dim-2 VQ of h2 ----------------
// vector (b,c): [h2[b,c], h2[b,256+c]], c in [0,256)
__global__ __launch_bounds__(256)
void fq22_kernel(const float* __restrict__ E)   // E: [2,512]
{
    __shared__ __align__(16) float sm0[512];
    __shared__ __align__(16) float sm1[512];
    __shared__ __align__(16) float sc2[512];
    const int tid = threadIdx.x;
    for (int e = tid; e < 512; e += 256) {
        float e0 = E[e], e1 = E[512 + e];
        sm0[e] = -2.f * e0;
        sm1[e] = -2.f * e1;
        sc2[e] = fmaf(e0, e0, e1 * e1);
    }
    __syncthreads();

    const int base = blockIdx.x * 1024 + tid;
    ull v0r[4], v1r[4];
    #pragma unroll
    for (int s = 0; s < 4; s++) {
        const int vid = base + s * 256;
        const int b = vid >> 8, c = vid & 255;
        float a0 = g_h2[(size_t)b * 512 + c];
        float a1 = g_h2[(size_t)b * 512 + 256 + c];
        v0r[s] = pack2(a0, a0);
        v1r[s] = pack2(a1, a1);
    }
    float bestd[4] = {1e30f, 1e30f, 1e30f, 1e30f};
    int   bg[4]    = {0, 0, 0, 0};
    #pragma unroll 2
    for (int u = 0; u < 128; u++) {
        const ull m0A = *(const ull*)&sm0[4 * u];
        const ull m0B = *(const ull*)&sm0[4 * u + 2];
        const ull m1A = *(const ull*)&sm1[4 * u];
        const ull m1B = *(const ull*)&sm1[4 * u + 2];
        const ull c2A = *(const ull*)&sc2[4 * u];
        const ull c2B = *(const ull*)&sc2[4 * u + 2];
        #pragma unroll
        for (int s = 0; s < 4; s++) {
            float2 fa = unpack2(ffma2(v0r[s], m0A, ffma2(v1r[s], m1A, c2A)));
            float2 fb = unpack2(ffma2(v0r[s], m0B, ffma2(v1r[s], m1B, c2B)));
            float m = fminf(fminf(fa.x, fa.y), fminf(fb.x, fb.y));
            if (m < bestd[s]) { bestd[s] = m; bg[s] = u; }
        }
    }
    float lsum = 0.f;
    #pragma unroll
    for (int s = 0; s < 4; s++) {
        const int u = bg[s];
        float2 fa = unpack2(ffma2(v0r[s], *(const ull*)&sm0[4 * u],
                      ffma2(v1r[s], *(const ull*)&sm1[4 * u], *(const ull*)&sc2[4 * u])));
        float2 fb = unpack2(ffma2(v0r[s], *(const ull*)&sm0[4 * u + 2],
                      ffma2(v1r[s], *(const ull*)&sm1[4 * u + 2], *(const ull*)&sc2[4 * u + 2])));
        int e = 4 * u;
        if      (fa.x == bestd[s]) e += 0;
        else if (fa.y == bestd[s]) e += 1;
        else if (fb.x == bestd[s]) e += 2;
        else                       e += 3;

        const int vid = base + s * 256;
        const int b = vid >> 8, c = vid & 255;
        float e0 = -0.5f * sm0[e];     // exact recovery of codeword
        float e1 = -0.5f * sm1[e];
        float v0 = unpack2(v0r[s]).x;
        float v1 = unpack2(v1r[s]).x;
        float d0 = e0 - v0, d1 = e1 - v1;
        lsum = fmaf(d0, d0, lsum);
        lsum = fmaf(d1, d1, lsum);
        g_qx2[(size_t)b * 512 + c]       = v0 + d0;
        g_qx2[(size_t)b * 512 + 256 + c] = v1 + d1;
    }
    block_sum_to(&g_dsum[2], lsum);
}

// ---------------- final: out = qx2 @ W3^T, plus diff scalar ----------------
__global__ __launch_bounds__(256)
void out_kernel(const float* __restrict__ W3, float* __restrict__ out, int out_size)
{
    __shared__ float sW3[10 * 512];
    const int tid = threadIdx.x;
    for (int i = tid; i < 5120; i += 256) sW3[i] = W3[i];
    __syncthreads();
    const int lane = tid & 31, warp = tid >> 5;
    const int b = blockIdx.x * 8 + warp;
    float p[10];
    #pragma unroll
    for (int k = 0; k < 10; k++) p[k] = 0.f;
    #pragma unroll
    for (int t = 0; t < 16; t++) {
        const int c = t * 32 + lane;
        float v = g_qx2[(size_t)b * 512 + c];
        #pragma unroll
        for (int k = 0; k < 10; k++) p[k] = fmaf(v, sW3[k * 512 + c], p[k]);
    }
    #pragma unroll
    for (int k = 0; k < 10; k++) {
        #pragma unroll
        for (int o = 16; o; o >>= 1) p[k] += __shfl_xor_sync(0xffffffffu, p[k], o);
    }
    if (lane == 0) {
        #pragma unroll
        for (int k = 0; k < 10; k++) out[b * 10 + k] = p[k];
    }
    if (blockIdx.x == 0 && tid == 0 && out_size > BATCH * 10) {
        double diff = g_dsum[0] * (1.0 / 2097152.0)
                    + g_dsum[2] * (1.0 / 2097152.0)
                    + g_dsum[1] * (1.0 / 262144.0);
        out[BATCH * 10] = (float)diff;
    }
}

// ---------------- launch ----------------
extern "C" void kernel_launch(void* const* d_in, const int* in_sizes, int n_in,
                              void* d_out, int out_size)
{
    const float* x      = (const float*)d_in[0];
    const float* W1     = (const float*)d_in[1];
    const float* W2     = (const float*)d_in[2];
    const float* W3     = (const float*)d_in[3];
    const float* gamma1 = (const float*)d_in[4];
    const float* beta1  = (const float*)d_in[5];
    const float* Ef21   = (const float*)d_in[6];
    const float* Eq2    = (const float*)d_in[7];
    const float* Ef22   = (const float*)d_in[8];
    float* out = (float*)d_out;

    gemm_kernel<784, false><<<dim3(8, 32), 256>>>(x, W1, nullptr, nullptr);   // h = relu(x@W1^T), zeros accums
    fq21_kernel<<<256, 256>>>(Ef21);                                           // h -> qx (+d_f21, +BN sums)
    wq_kernel<<<256, 256>>>(W2, Eq2);                                          // W2 -> qW2 (+d2)
    gemm_kernel<512, true><<<dim3(8, 32), 256>>>(nullptr, nullptr, gamma1, beta1); // h2 = relu(bn(qx)@qW2^T)
    fq22_kernel<<<1024, 256>>>(Ef22);                                          // h2 -> qx2 (+d_f22)
    out_kernel<<<512, 256>>>(W3, out, out_size);                               // logits + diff scalar
}

// round 6
// speedup vs baseline: 1.2560x; 1.2560x over previous
#include <cuda_runtime.h>

typedef unsigned long long ull;

#define BATCH 4096

// ---------------- device scratch (no allocations allowed) ----------------
__device__ float g_h  [BATCH * 512];
__device__ float g_qx [BATCH * 512];
__device__ float g_qW2[512 * 512];
__device__ float g_h2 [BATCH * 512];
__device__ float g_qx2[BATCH * 512];
__device__ double g_bnsum[512];
__device__ double g_bnsq [512];
__device__ double g_dsum[3];   // [0]=fq21 sum, [1]=wq sum, [2]=fq22 sum

// ---------------- packed f32x2 helpers (Blackwell FFMA2) ----------------
__device__ __forceinline__ ull pack2(float x, float y) {
    ull r;
    unsigned xu = __float_as_uint(x), yu = __float_as_uint(y);
    asm("mov.b64 %0, {%1, %2};" : "=l"(r) : "r"(xu), "r"(yu));
    return r;
}
__device__ __forceinline__ float2 unpack2(ull v) {
    unsigned lo, hi;
    asm("mov.b64 {%0, %1}, %2;" : "=r"(lo), "=r"(hi) : "l"(v));
    float2 f; f.x = __uint_as_float(lo); f.y = __uint_as_float(hi);
    return f;
}
__device__ __forceinline__ ull ffma2(ull a, ull b, ull c) {
    ull d;
    asm("fma.rn.f32x2 %0, %1, %2, %3;" : "=l"(d) : "l"(a), "l"(b), "l"(c));
    return d;
}

// ---------------- block reduce -> atomic double ----------------
__device__ __forceinline__ void block_sum_to(double* target, float v) {
    __shared__ float red[8];
    const int tid = threadIdx.x;
    #pragma unroll
    for (int o = 16; o; o >>= 1) v += __shfl_xor_sync(0xffffffffu, v, o);
    if ((tid & 31) == 0) red[tid >> 5] = v;
    __syncthreads();
    if (tid == 0) {
        float s = 0.f;
        const int nw = (blockDim.x + 31) >> 5;
        for (int w = 0; w < nw; w++) s += red[w];
        atomicAdd(target, (double)s);
    }
}

// ---------------- GEMM: C[m,n] = relu( sum_k f(A[m,k]) * W[n,k] ) ----------------
// BM=128, BN=64, BK=16, 128 threads, per-thread 8m x 8n with FFMA2 over m-pairs.
// Register-prefetch double-buffered smem, ONE barrier per k-tile.
// AFFINE: A transformed as A*scale[k]+shift[k] (fused BN from g_bnsum/g_bnsq).
template<int KDIM, bool AFFINE>
__global__ __launch_bounds__(128, 2)
void gemm_kernel(const float* __restrict__ Aext, const float* __restrict__ Wext,
                 const float* __restrict__ gamma, const float* __restrict__ beta)
{
    const float* __restrict__ A = AFFINE ? (const float*)g_qx  : Aext;
    const float* __restrict__ W = AFFINE ? (const float*)g_qW2 : Wext;
    float*       __restrict__ C = AFFINE ? (float*)g_h2 : (float*)g_h;

    __shared__ __align__(16) float As[2][16][132];
    __shared__ __align__(16) float Bs[2][16][68];
    __shared__ __align__(16) float sScale[AFFINE ? 512 : 4];
    __shared__ __align__(16) float sShift[AFFINE ? 512 : 4];

    const int tid  = threadIdx.x;
    const int tx   = tid & 7;     // n group (8 cols)
    const int ty   = tid >> 3;    // m group (8 rows)
    const int m0   = blockIdx.y * 128;
    const int n0   = blockIdx.x * 64;
    const int arow = tid >> 2;    // 0..31 (loader row base)
    const int akq  = tid & 3;     // k quad

    if (AFFINE) {
        for (int c = tid; c < 512; c += 128) {
            float S  = (float)g_bnsum[c];
            float S2 = (float)g_bnsq[c];
            float mu  = S * (1.f / BATCH);
            float var = fmaf(-mu, mu, S2 * (1.f / BATCH));
            float sc  = gamma[c] * rsqrtf(var + 1e-5f);
            sScale[c] = sc;
            sShift[c] = fmaf(-mu, sc, beta[c]);
        }
        __syncthreads();
    } else if (blockIdx.x == 0 && blockIdx.y == 0) {
        // first kernel in the graph: zero all accumulators
        for (int i = tid; i < 512; i += 128) { g_bnsum[i] = 0.0; g_bnsq[i] = 0.0; }
        if (tid < 3) g_dsum[tid] = 0.0;
    }

    constexpr int NT = KDIM / 16;
    float4 pa[4], pb[2];

    // prefetch tile 0
    #pragma unroll
    for (int l = 0; l < 4; l++)
        pa[l] = *(const float4*)(A + (size_t)(m0 + arow + l * 32) * KDIM + akq * 4);
    #pragma unroll
    for (int l = 0; l < 2; l++)
        pb[l] = *(const float4*)(W + (size_t)(n0 + arow + l * 32) * KDIM + akq * 4);

    #define STORE_TILE(buf, ktv) do {                                            \
        _Pragma("unroll")                                                        \
        for (int l = 0; l < 4; l++) {                                            \
            float4 av = pa[l];                                                   \
            if (AFFINE) {                                                        \
                float4 sc = *(const float4*)&sScale[(ktv) * 16 + akq * 4];       \
                float4 sh = *(const float4*)&sShift[(ktv) * 16 + akq * 4];       \
                av.x = fmaf(av.x, sc.x, sh.x);                                   \
                av.y = fmaf(av.y, sc.y, sh.y);                                   \
                av.z = fmaf(av.z, sc.z, sh.z);                                   \
                av.w = fmaf(av.w, sc.w, sh.w);                                   \
            }                                                                    \
            As[buf][akq * 4 + 0][arow + l * 32] = av.x;                          \
            As[buf][akq * 4 + 1][arow + l * 32] = av.y;                          \
            As[buf][akq * 4 + 2][arow + l * 32] = av.z;                          \
            As[buf][akq * 4 + 3][arow + l * 32] = av.w;                          \
        }                                                                        \
        _Pragma("unroll")                                                        \
        for (int l = 0; l < 2; l++) {                                            \
            float4 bv = pb[l];                                                   \
            Bs[buf][akq * 4 + 0][arow + l * 32] = bv.x;                          \
            Bs[buf][akq * 4 + 1][arow + l * 32] = bv.y;                          \
            Bs[buf][akq * 4 + 2][arow + l * 32] = bv.z;                          \
            Bs[buf][akq * 4 + 3][arow + l * 32] = bv.w;                          \
        }                                                                        \
    } while (0)

    STORE_TILE(0, 0);
    __syncthreads();

    ull acc[4][8];
    #pragma unroll
    for (int p = 0; p < 4; p++)
        #pragma unroll
        for (int n = 0; n < 8; n++) acc[p][n] = 0ull;

    for (int kt = 0; kt < NT; kt++) {
        const int cur = kt & 1;
        if (kt + 1 < NT) {
            #pragma unroll
            for (int l = 0; l < 4; l++)
                pa[l] = *(const float4*)(A + (size_t)(m0 + arow + l * 32) * KDIM
                                         + (kt + 1) * 16 + akq * 4);
            #pragma unroll
            for (int l = 0; l < 2; l++)
                pb[l] = *(const float4*)(W + (size_t)(n0 + arow + l * 32) * KDIM
                                         + (kt + 1) * 16 + akq * 4);
        }
        #pragma unroll
        for (int k = 0; k < 16; k++) {
            // A m-pairs are contiguous in smem: direct 128-bit loads, natural ull pairs
            const float4 a0 = *(const float4*)&As[cur][k][ty * 8];
            const float4 a1 = *(const float4*)&As[cur][k][ty * 8 + 4];
            const float4 b0 = *(const float4*)&Bs[cur][k][tx * 8];
            const float4 b1 = *(const float4*)&Bs[cur][k][tx * 8 + 4];
            ull ap0 = pack2(a0.x, a0.y);
            ull ap1 = pack2(a0.z, a0.w);
            ull ap2 = pack2(a1.x, a1.y);
            ull ap3 = pack2(a1.z, a1.w);
            float bv[8] = { b0.x, b0.y, b0.z, b0.w, b1.x, b1.y, b1.z, b1.w };
            #pragma unroll
            for (int n = 0; n < 8; n++) {
                ull bb = pack2(bv[n], bv[n]);
                acc[0][n] = ffma2(ap0, bb, acc[0][n]);
                acc[1][n] = ffma2(ap1, bb, acc[1][n]);
                acc[2][n] = ffma2(ap2, bb, acc[2][n]);
                acc[3][n] = ffma2(ap3, bb, acc[3][n]);
            }
        }
        if (kt + 1 < NT) {
            // safe with ONE barrier: this iteration read `cur` only; `cur^1`'s
            // last readers (iteration kt-1) all passed the previous barrier.
            STORE_TILE(cur ^ 1, kt + 1);
            __syncthreads();
        }
    }
    #undef STORE_TILE

    // epilogue: relu + store (rows come in m-pairs)
    #pragma unroll
    for (int p = 0; p < 4; p++) {
        const int r0 = m0 + ty * 8 + 2 * p;
        float v0[8], v1[8];
        #pragma unroll
        for (int n = 0; n < 8; n++) {
            float2 f = unpack2(acc[p][n]);
            v0[n] = fmaxf(f.x, 0.f);
            v1[n] = fmaxf(f.y, 0.f);
        }
        *(float4*)(C + (size_t)r0 * 512 + n0 + tx * 8)           = make_float4(v0[0], v0[1], v0[2], v0[3]);
        *(float4*)(C + (size_t)r0 * 512 + n0 + tx * 8 + 4)       = make_float4(v0[4], v0[5], v0[6], v0[7]);
        *(float4*)(C + (size_t)(r0 + 1) * 512 + n0 + tx * 8)     = make_float4(v1[0], v1[1], v1[2], v1[3]);
        *(float4*)(C + (size_t)(r0 + 1) * 512 + n0 + tx * 8 + 4) = make_float4(v1[4], v1[5], v1[6], v1[7]);
    }
}

// ---------------- fq21: dim-8 VQ of h (strided groups) + fused BN stats ----------------
// vector (b,c): v_j = h[b, j*64+c].  4 vectors/thread, 4-code groups, group-min + index recovery.
__global__ __launch_bounds__(256, 2)
void fq21_kernel(const float* __restrict__ E)   // E: [8,512]
{
    __shared__ __align__(16) float sE[8][512];
    __shared__ __align__(16) float sC2[512];
    __shared__ float sBS[4][512];   // per-quadrant column sums
    __shared__ float sBQ[4][512];   // per-quadrant column sq-sums
    const int tid = threadIdx.x;
    for (int i = tid; i < 8 * 512; i += 256) ((float*)sE)[i] = E[i];
    __syncthreads();
    for (int e = tid; e < 512; e += 256) {
        float s = 0.f;
        #pragma unroll
        for (int j = 0; j < 8; j++) s = fmaf(sE[j][e], sE[j][e], s);
        sC2[e] = s;
    }
    __syncthreads();

    const int base = blockIdx.x * 1024 + tid;
    ull vr[4][8];
    #pragma unroll
    for (int s = 0; s < 4; s++) {
        const int vid = base + s * 256;
        const int b = vid >> 6, c = vid & 63;
        #pragma unroll
        for (int j = 0; j < 8; j++) {
            float v = g_h[(size_t)b * 512 + j * 64 + c];
            vr[s][j] = pack2(v, v);
        }
    }

    float bestd[4] = {1e30f, 1e30f, 1e30f, 1e30f};
    int   bg[4]    = {0, 0, 0, 0};
    const ull M2 = pack2(-2.f, -2.f);

    #pragma unroll 2
    for (int u = 0; u < 128; u++) {
        const ull c2A = *(const ull*)&sC2[4 * u];
        const ull c2B = *(const ull*)&sC2[4 * u + 2];
        ull a[4], b2[4];
        {
            const ull eA = *(const ull*)&sE[0][4 * u];
            const ull eB = *(const ull*)&sE[0][4 * u + 2];
            #pragma unroll
            for (int s = 0; s < 4; s++) {
                a [s] = ffma2(vr[s][0], eA, 0ull);
                b2[s] = ffma2(vr[s][0], eB, 0ull);
            }
        }
        #pragma unroll
        for (int j = 1; j < 8; j++) {
            const ull eA = *(const ull*)&sE[j][4 * u];
            const ull eB = *(const ull*)&sE[j][4 * u + 2];
            #pragma unroll
            for (int s = 0; s < 4; s++) {
                a [s] = ffma2(vr[s][j], eA, a [s]);
                b2[s] = ffma2(vr[s][j], eB, b2[s]);
            }
        }
        #pragma unroll
        for (int s = 0; s < 4; s++) {
            float2 fa = unpack2(ffma2(M2, a [s], c2A));
            float2 fb = unpack2(ffma2(M2, b2[s], c2B));
            float m = fminf(fminf(fa.x, fa.y), fminf(fb.x, fb.y));
            if (m < bestd[s]) { bestd[s] = m; bg[s] = u; }
        }
    }

    // index recovery + straight-through write + BN private accumulation
    float priv_s[8], priv_q[8];
    #pragma unroll
    for (int j = 0; j < 8; j++) { priv_s[j] = 0.f; priv_q[j] = 0.f; }
    float lsum = 0.f;
    #pragma unroll
    for (int s = 0; s < 4; s++) {
        const int u = bg[s];
        ull a = 0ull, b2 = 0ull;
        #pragma unroll
        for (int j = 0; j < 8; j++) {
            a  = ffma2(vr[s][j], *(const ull*)&sE[j][4 * u],     a);
            b2 = ffma2(vr[s][j], *(const ull*)&sE[j][4 * u + 2], b2);
        }
        float2 fa = unpack2(ffma2(M2, a,  *(const ull*)&sC2[4 * u]));
        float2 fb = unpack2(ffma2(M2, b2, *(const ull*)&sC2[4 * u + 2]));
        int e = 4 * u;
        if      (fa.x == bestd[s]) e += 0;
        else if (fa.y == bestd[s]) e += 1;
        else if (fb.x == bestd[s]) e += 2;
        else                       e += 3;

        const int vid = base + s * 256;
        const int b = vid >> 6, c = vid & 63;
        #pragma unroll
        for (int j = 0; j < 8; j++) {
            float v  = unpack2(vr[s][j]).x;
            float dq = sE[j][e] - v;
            lsum = fmaf(dq, dq, lsum);
            float qst = v + dq;                      // straight-through value
            g_qx[(size_t)b * 512 + j * 64 + c] = qst;
            priv_s[j] += qst;
            priv_q[j]  = fmaf(qst, qst, priv_q[j]);
        }
    }

    // BN slab reduce: column = j*64 + (tid&63); quadrant q = tid>>6
    {
        const int q = tid >> 6, c = tid & 63;
        #pragma unroll
        for (int j = 0; j < 8; j++) {
            sBS[q][j * 64 + c] = priv_s[j];
            sBQ[q][j * 64 + c] = priv_q[j];
        }
    }
    __syncthreads();
    for (int cell = tid; cell < 512; cell += 256) {
        float s  = sBS[0][cell] + sBS[1][cell] + sBS[2][cell] + sBS[3][cell];
        float s2 = sBQ[0][cell] + sBQ[1][cell] + sBQ[2][cell] + sBQ[3][cell];
        atomicAdd(&g_bnsum[cell], (double)s);
        atomicAdd(&g_bnsq [cell], (double)s2);
    }
    block_sum_to(&g_dsum[0], lsum);
}

// ---------------- weight VQ of W2 (dim-16 groups), 4 threads per vector ----------------
__global__ __launch_bounds__(256)
void wq_kernel(const float* __restrict__ W2, const float* __restrict__ E)
{
    __shared__ __align__(16) float sE[16][512];
    __shared__ __align__(16) float sC2[512];
    const int tid = threadIdx.x;
    for (int i = tid; i < 16 * 512; i += 256) ((float*)sE)[i] = E[i];
    __syncthreads();
    for (int e = tid; e < 512; e += 256) {
        float s = 0.f;
        #pragma unroll
        for (int k = 0; k < 16; k++) s = fmaf(sE[k][e], sE[k][e], s);
        sC2[e] = s;
    }
    __syncthreads();

    const int vec   = blockIdx.x * 64 + (tid >> 2);   // 0..16383
    const int slice = tid & 3;
    const int g = vec >> 6, c = vec & 63;

    ull vr[16];
    #pragma unroll
    for (int k = 0; k < 16; k++) {
        float v = W2[(size_t)(g * 2 + (k & 1)) * 512 + c * 8 + (k >> 1)];
        vr[k] = pack2(v, v);
    }

    float bestd = 1e30f; int bg = slice;
    const ull M2 = pack2(-2.f, -2.f);
    #pragma unroll 2
    for (int uu = 0; uu < 32; uu++) {
        const int u = 4 * uu + slice;
        ull a = 0ull, b2 = 0ull;
        #pragma unroll
        for (int k = 0; k < 16; k++) {
            a  = ffma2(vr[k], *(const ull*)&sE[k][4 * u],     a);
            b2 = ffma2(vr[k], *(const ull*)&sE[k][4 * u + 2], b2);
        }
        float2 fa = unpack2(ffma2(M2, a,  *(const ull*)&sC2[4 * u]));
        float2 fb = unpack2(ffma2(M2, b2, *(const ull*)&sC2[4 * u + 2]));
        float m = fminf(fminf(fa.x, fa.y), fminf(fb.x, fb.y));
        if (m < bestd) { bestd = m; bg = u; }
    }
    int idx;
    {
        ull a = 0ull, b2 = 0ull;
        #pragma unroll
        for (int k = 0; k < 16; k++) {
            a  = ffma2(vr[k], *(const ull*)&sE[k][4 * bg],     a);
            b2 = ffma2(vr[k], *(const ull*)&sE[k][4 * bg + 2], b2);
        }
        float2 fa = unpack2(ffma2(M2, a,  *(const ull*)&sC2[4 * bg]));
        float2 fb = unpack2(ffma2(M2, b2, *(const ull*)&sC2[4 * bg + 2]));
        idx = 4 * bg;
        if      (fa.x == bestd) idx += 0;
        else if (fa.y == bestd) idx += 1;
        else if (fb.x == bestd) idx += 2;
        else                    idx += 3;
    }
    #pragma unroll
    for (int off = 1; off < 4; off <<= 1) {
        float od = __shfl_xor_sync(0xffffffffu, bestd, off);
        int   oi = __shfl_xor_sync(0xffffffffu, idx,   off);
        if (od < bestd || (od == bestd && oi < idx)) { bestd = od; idx = oi; }
    }
    #pragma unroll
    for (int kk = 0; kk < 4; kk++) {
        int k = slice * 4 + kk;
        float v  = unpack2(vr[k]).x;
        float dq = sE[k][idx] - v;
        g_qW2[(size_t)(g * 2 + (k & 1)) * 512 + c * 8 + (k >> 1)] = v + dq;
    }
    float lsum = 0.f;
    if (slice == 0) {
        #pragma unroll
        for (int k = 0; k < 16; k++) {
            float v  = unpack2(vr[k]).x;
            float dq = sE[k][idx] - v;
            lsum = fmaf(dq, dq, lsum);
        }
    }
    block_sum_to(&g_dsum[1], lsum);
}

// ---------------- fq22: dim-2 VQ of h2 ----------------
__global__ __launch_bounds__(256)
void fq22_kernel(const float* __restrict__ E)   // E: [2,512]
{
    __shared__ __align__(16) float sm0[512];
    __shared__ __align__(16) float sm1[512];
    __shared__ __align__(16) float sc2[512];
    const int tid = threadIdx.x;
    for (int e = tid; e < 512; e += 256) {
        float e0 = E[e], e1 = E[512 + e];
        sm0[e] = -2.f * e0;
        sm1[e] = -2.f * e1;
        sc2[e] = fmaf(e0, e0, e1 * e1);
    }
    __syncthreads();

    const int base = blockIdx.x * 1024 + tid;
    ull v0r[4], v1r[4];
    #pragma unroll
    for (int s = 0; s < 4; s++) {
        const int vid = base + s * 256;
        const int b = vid >> 8, c = vid & 255;
        float a0 = g_h2[(size_t)b * 512 + c];
        float a1 = g_h2[(size_t)b * 512 + 256 + c];
        v0r[s] = pack2(a0, a0);
        v1r[s] = pack2(a1, a1);
    }
    float bestd[4] = {1e30f, 1e30f, 1e30f, 1e30f};
    int   bg[4]    = {0, 0, 0, 0};
    #pragma unroll 2
    for (int u = 0; u < 128; u++) {
        const ull m0A = *(const ull*)&sm0[4 * u];
        const ull m0B = *(const ull*)&sm0[4 * u + 2];
        const ull m1A = *(const ull*)&sm1[4 * u];
        const ull m1B = *(const ull*)&sm1[4 * u + 2];
        const ull c2A = *(const ull*)&sc2[4 * u];
        const ull c2B = *(const ull*)&sc2[4 * u + 2];
        #pragma unroll
        for (int s = 0; s < 4; s++) {
            float2 fa = unpack2(ffma2(v0r[s], m0A, ffma2(v1r[s], m1A, c2A)));
            float2 fb = unpack2(ffma2(v0r[s], m0B, ffma2(v1r[s], m1B, c2B)));
            float m = fminf(fminf(fa.x, fa.y), fminf(fb.x, fb.y));
            if (m < bestd[s]) { bestd[s] = m; bg[s] = u; }
        }
    }
    float lsum = 0.f;
    #pragma unroll
    for (int s = 0; s < 4; s++) {
        const int u = bg[s];
        float2 fa = unpack2(ffma2(v0r[s], *(const ull*)&sm0[4 * u],
                      ffma2(v1r[s], *(const ull*)&sm1[4 * u], *(const ull*)&sc2[4 * u])));
        float2 fb = unpack2(ffma2(v0r[s], *(const ull*)&sm0[4 * u + 2],
                      ffma2(v1r[s], *(const ull*)&sm1[4 * u + 2], *(const ull*)&sc2[4 * u + 2])));
        int e = 4 * u;
        if      (fa.x == bestd[s]) e += 0;
        else if (fa.y == bestd[s]) e += 1;
        else if (fb.x == bestd[s]) e += 2;
        else                       e += 3;

        const int vid = base + s * 256;
        const int b = vid >> 8, c = vid & 255;
        float e0 = -0.5f * sm0[e];     // exact recovery of codeword
        float e1 = -0.5f * sm1[e];
        float v0 = unpack2(v0r[s]).x;
        float v1 = unpack2(v1r[s]).x;
        float d0 = e0 - v0, d1 = e1 - v1;
        lsum = fmaf(d0, d0, lsum);
        lsum = fmaf(d1, d1, lsum);
        g_qx2[(size_t)b * 512 + c]       = v0 + d0;
        g_qx2[(size_t)b * 512 + 256 + c] = v1 + d1;
    }
    block_sum_to(&g_dsum[2], lsum);
}

// ---------------- final: out = qx2 @ W3^T, plus diff scalar ----------------
__global__ __launch_bounds__(256)
void out_kernel(const float* __restrict__ W3, float* __restrict__ out, int out_size)
{
    __shared__ float sW3[10 * 512];
    const int tid = threadIdx.x;
    for (int i = tid; i < 5120; i += 256) sW3[i] = W3[i];
    __syncthreads();
    const int lane = tid & 31, warp = tid >> 5;
    const int b = blockIdx.x * 8 + warp;
    float p[10];
    #pragma unroll
    for (int k = 0; k < 10; k++) p[k] = 0.f;
    #pragma unroll
    for (int t = 0; t < 16; t++) {
        const int c = t * 32 + lane;
        float v = g_qx2[(size_t)b * 512 + c];
        #pragma unroll
        for (int k = 0; k < 10; k++) p[k] = fmaf(v, sW3[k * 512 + c], p[k]);
    }
    #pragma unroll
    for (int k = 0; k < 10; k++) {
        #pragma unroll
        for (int o = 16; o; o >>= 1) p[k] += __shfl_xor_sync(0xffffffffu, p[k], o);
    }
    if (lane == 0) {
        #pragma unroll
        for (int k = 0; k < 10; k++) out[b * 10 + k] = p[k];
    }
    if (blockIdx.x == 0 && tid == 0 && out_size > BATCH * 10) {
        double diff = g_dsum[0] * (1.0 / 2097152.0)
                    + g_dsum[2] * (1.0 / 2097152.0)
                    + g_dsum[1] * (1.0 / 262144.0);
        out[BATCH * 10] = (float)diff;
    }
}

// ---------------- launch ----------------
extern "C" void kernel_launch(void* const* d_in, const int* in_sizes, int n_in,
                              void* d_out, int out_size)
{
    const float* x      = (const float*)d_in[0];
    const float* W1     = (const float*)d_in[1];
    const float* W2     = (const float*)d_in[2];
    const float* W3     = (const float*)d_in[3];
    const float* gamma1 = (const float*)d_in[4];
    const float* beta1  = (const float*)d_in[5];
    const float* Ef21   = (const float*)d_in[6];
    const float* Eq2    = (const float*)d_in[7];
    const float* Ef22   = (const float*)d_in[8];
    float* out = (float*)d_out;

    gemm_kernel<784, false><<<dim3(8, 32), 128>>>(x, W1, nullptr, nullptr);        // h = relu(x@W1^T)
    fq21_kernel<<<256, 256>>>(Ef21);                                                // h -> qx (+d_f21, +BN)
    wq_kernel<<<256, 256>>>(W2, Eq2);                                               // W2 -> qW2 (+d2)
    gemm_kernel<512, true><<<dim3(8, 32), 128>>>(nullptr, nullptr, gamma1, beta1);  // h2 = relu(bn(qx)@qW2^T)
    fq22_kernel<<<1024, 256>>>(Ef22);                                               // h2 -> qx2 (+d_f22)
    out_kernel<<<512, 256>>>(W3, out, out_size);                                    // logits + diff scalar
}